// round 6
// baseline (speedup 1.0000x reference)
#include <cuda_runtime.h>
#include <cuda_bf16.h>
#include <cstdint>

#define RELS 3
#define F 128
#define KTOT (RELS * F)          // 384
#define NMAX 50000
#define EMAX 800000

// ---------------- scratch (static device globals; no allocation) ----------------
__device__ float g_AGG[(size_t)NMAX * KTOT];      // [n][r*F+f]  76.8 MB
__device__ float g_H[(size_t)NMAX * F];           // layer-1 output
__device__ float g_NQ[NMAX * RELS];
__device__ float g_NK[NMAX * RELS];
__device__ float g_EX[EMAX];
__device__ float g_WQ[2 * RELS * F];
__device__ float g_WK[2 * RELS * F];
__device__ float g_CE[2];
// CSR scratch
__device__ int   g_CNT[NMAX];
__device__ int   g_ROWPTR[NMAX + 1];
__device__ int   g_PART[NMAX];
__device__ int   g_BSUM[1024];
__device__ int   g_NKIDX[EMAX];                   // sorted: src*RELS + et
__device__ float g_SEA[EMAX];                     // sorted: edge_attr

// ---------------- prep: wq/wk vectors + edge scalar ----------------
__global__ void prep_kernel(const float* __restrict__ w1, const float* __restrict__ q1,
                            const float* __restrict__ k1,
                            const float* __restrict__ w2, const float* __restrict__ q2,
                            const float* __restrict__ k2,
                            const float* __restrict__ we1, const float* __restrict__ e1,
                            const float* __restrict__ we2, const float* __restrict__ e2) {
    int idx = blockIdx.x * blockDim.x + threadIdx.x;
    if (idx < 4 * RELS * F) {
        int which = idx / (RELS * F);
        int rem   = idx % (RELS * F);
        const float* w = (which < 2) ? w1 : w2;
        const float* v = (which == 0) ? q1 : (which == 1) ? k1 : (which == 2) ? q2 : k2;
        const float* row = w + (size_t)rem * F;
        float s = 0.f;
        #pragma unroll 8
        for (int o = 0; o < F; o++) s += row[o] * v[o];
        float* d = (which == 0) ? g_WQ
                 : (which == 1) ? g_WK
                 : (which == 2) ? (g_WQ + RELS * F)
                 : (g_WK + RELS * F);
        d[rem] = s;
    } else if (idx == 4 * RELS * F) {
        float s = 0.f;
        for (int o = 0; o < F; o++) s += we1[o] * e1[o];
        g_CE[0] = s;
    } else if (idx == 4 * RELS * F + 1) {
        float s = 0.f;
        for (int o = 0; o < F; o++) s += we2[o] * e2[o];
        g_CE[1] = s;
    }
}

// ---------------- CSR build ----------------
__global__ void zero_cnt_kernel(int Nn) {
    int i = blockIdx.x * blockDim.x + threadIdx.x;
    if (i < Nn) g_CNT[i] = 0;
}
__global__ void hist_kernel(const int* __restrict__ dst, int Ecnt) {
    int e = blockIdx.x * blockDim.x + threadIdx.x;
    if (e < Ecnt) atomicAdd(&g_CNT[dst[e]], 1);
}
__global__ void scan1_kernel(int Nn) {
    __shared__ int sh[256];
    int i = blockIdx.x * 256 + threadIdx.x;
    int v = (i < Nn) ? g_CNT[i] : 0;
    sh[threadIdx.x] = v;
    __syncthreads();
    #pragma unroll
    for (int off = 1; off < 256; off <<= 1) {
        int t = (threadIdx.x >= off) ? sh[threadIdx.x - off] : 0;
        __syncthreads();
        sh[threadIdx.x] += t;
        __syncthreads();
    }
    if (i < Nn) g_PART[i] = sh[threadIdx.x] - v;
    if (threadIdx.x == 255) g_BSUM[blockIdx.x] = sh[255];
}
__global__ void scan2_kernel(int nb) {
    __shared__ int sh[1024];
    int v = (threadIdx.x < nb) ? g_BSUM[threadIdx.x] : 0;
    sh[threadIdx.x] = v;
    __syncthreads();
    #pragma unroll
    for (int off = 1; off < 1024; off <<= 1) {
        int t = (threadIdx.x >= off) ? sh[threadIdx.x - off] : 0;
        __syncthreads();
        sh[threadIdx.x] += t;
        __syncthreads();
    }
    if (threadIdx.x < nb) g_BSUM[threadIdx.x] = sh[threadIdx.x] - v;
}
__global__ void scan3_kernel(int Nn, int Ecnt) {
    int i = blockIdx.x * blockDim.x + threadIdx.x;
    if (i < Nn) {
        g_ROWPTR[i] = g_PART[i] + g_BSUM[i >> 8];
        g_CNT[i] = 0;
    }
    if (i == Nn) g_ROWPTR[Nn] = Ecnt;
}
__global__ void scatter_kernel(const int* __restrict__ src, const int* __restrict__ dst,
                               const int* __restrict__ et, const float* __restrict__ ea,
                               int Ecnt) {
    int e = blockIdx.x * blockDim.x + threadIdx.x;
    if (e >= Ecnt) return;
    int d = dst[e];
    int pos = g_ROWPTR[d] + atomicAdd(&g_CNT[d], 1);
    g_NKIDX[pos] = src[e] * RELS + et[e];
    g_SEA[pos]   = ea[e];
}

// ---------------- per-node attention logits ----------------
__global__ __launch_bounds__(256) void nqnk_kernel(const float* __restrict__ xin,
                                                   int use_h, int layer, int Nn) {
    __shared__ float swq[RELS * F];
    __shared__ float swk[RELS * F];
    const float* X = use_h ? g_H : xin;
    const float* WQ = g_WQ + layer * RELS * F;
    const float* WK = g_WK + layer * RELS * F;
    for (int i = threadIdx.x; i < RELS * F; i += blockDim.x) {
        swq[i] = WQ[i];
        swk[i] = WK[i];
    }
    __syncthreads();

    int warp = (blockIdx.x * blockDim.x + threadIdx.x) >> 5;
    int lane = threadIdx.x & 31;
    if (warp >= Nn) return;

    const float* xr = X + (size_t)warp * F;
    float x0 = xr[lane], x1 = xr[lane + 32], x2 = xr[lane + 64], x3 = xr[lane + 96];

    #pragma unroll
    for (int r = 0; r < RELS; r++) {
        const float* wq = swq + r * F;
        const float* wk = swk + r * F;
        float sq = x0 * wq[lane] + x1 * wq[lane + 32] + x2 * wq[lane + 64] + x3 * wq[lane + 96];
        float sk = x0 * wk[lane] + x1 * wk[lane + 32] + x2 * wk[lane + 64] + x3 * wk[lane + 96];
        #pragma unroll
        for (int off = 16; off; off >>= 1) {
            sq += __shfl_down_sync(0xffffffffu, sq, off);
            sk += __shfl_down_sync(0xffffffffu, sk, off);
        }
        if (lane == 0) {
            g_NQ[warp * RELS + r] = sq;
            g_NK[warp * RELS + r] = sk;
        }
    }
}

// ------- fused softmax + per-relation x-aggregation, warp per dst node -------
// AGG[node][r*F+f] = sum over edges of type r: attn * x[src][f]
__global__ __launch_bounds__(256) void fused_agg_kernel(const float* __restrict__ xin,
                                                        int use_h, int layer, int Nn) {
    int node = (blockIdx.x * blockDim.x + threadIdx.x) >> 5;
    int lane = threadIdx.x & 31;
    if (node >= Nn) return;
    const float* X = use_h ? g_H : xin;

    int start = g_ROWPTR[node];
    int end   = g_ROWPTR[node + 1];
    float ce  = g_CE[layer];
    float nq0 = g_NQ[node * RELS + 0];
    float nq1 = g_NQ[node * RELS + 1];
    float nq2 = g_NQ[node * RELS + 2];

    // phase 1: lane-parallel exp + denominator
    float denom = 0.f;
    for (int i = start + lane; i < end; i += 32) {
        int nkidx = g_NKIDX[i];
        int s3 = nkidx / RELS;
        int t = nkidx - s3 * RELS;
        float nq = (t == 0) ? nq0 : (t == 1) ? nq1 : nq2;
        float a = nq + g_NK[nkidx] + ce * g_SEA[i];
        a = (a > 0.f) ? a : 0.2f * a;
        float ex = expf(a);
        g_EX[i] = ex;
        denom += ex;
    }
    #pragma unroll
    for (int off = 16; off; off >>= 1)
        denom += __shfl_xor_sync(0xffffffffu, denom, off);
    float inv = 1.f / (denom + 1e-16f);

    // phase 2: warp-per-edge, lanes over features; accumulate per relation
    float4 a0 = make_float4(0.f, 0.f, 0.f, 0.f);
    float4 a1 = make_float4(0.f, 0.f, 0.f, 0.f);
    float4 a2 = make_float4(0.f, 0.f, 0.f, 0.f);
    for (int i = start; i < end; i++) {
        int nkidx = g_NKIDX[i];           // warp-uniform
        int s = nkidx / RELS;
        int t = nkidx - s * RELS;
        float at = g_EX[i] * inv;
        float4 v = ((const float4*)(X + (size_t)s * F))[lane];
        if (t == 0) {
            a0.x += at * v.x; a0.y += at * v.y; a0.z += at * v.z; a0.w += at * v.w;
        } else if (t == 1) {
            a1.x += at * v.x; a1.y += at * v.y; a1.z += at * v.z; a1.w += at * v.w;
        } else {
            a2.x += at * v.x; a2.y += at * v.y; a2.z += at * v.z; a2.w += at * v.w;
        }
    }
    float4* ag = (float4*)(g_AGG + (size_t)node * KTOT);
    ag[lane]      = a0;
    ag[lane + 32] = a1;
    ag[lane + 64] = a2;
}

// ============== mma.sync bf16 GEMM, K=384 chunked: OUT = AGG @ Wstack + b ==============
#define APITCH 68
#define TILE_WORDS (128 * APITCH)
#define GEMM_SMEM_TOTAL (4 * TILE_WORDS * 4)

__device__ __forceinline__ uint32_t pack_split_hi(float x, float y) {
    __nv_bfloat16 hx = __float2bfloat16_rn(x);
    __nv_bfloat16 hy = __float2bfloat16_rn(y);
    return ((uint32_t)*(uint16_t*)&hy << 16) | (uint32_t)*(uint16_t*)&hx;
}
__device__ __forceinline__ uint32_t pack_split_lo(float x, float y) {
    __nv_bfloat16 hx = __float2bfloat16_rn(x);
    __nv_bfloat16 hy = __float2bfloat16_rn(y);
    __nv_bfloat16 lx = __float2bfloat16_rn(x - __bfloat162float(hx));
    __nv_bfloat16 ly = __float2bfloat16_rn(y - __bfloat162float(hy));
    return ((uint32_t)*(uint16_t*)&ly << 16) | (uint32_t)*(uint16_t*)&lx;
}
__device__ __forceinline__ void mma16816(float* d, const uint32_t* a, const uint32_t* b) {
    asm volatile("mma.sync.aligned.m16n8k16.row.col.f32.bf16.bf16.f32 "
                 "{%0,%1,%2,%3}, {%4,%5,%6,%7}, {%8,%9}, {%0,%1,%2,%3};"
                 : "+f"(d[0]), "+f"(d[1]), "+f"(d[2]), "+f"(d[3])
                 : "r"(a[0]), "r"(a[1]), "r"(a[2]), "r"(a[3]), "r"(b[0]), "r"(b[1]));
}

__global__ __launch_bounds__(256) void gemm_mma_kernel(const float* __restrict__ W,
                                                       const float* __restrict__ bias,
                                                       float* __restrict__ outp,
                                                       int relu, int Nn) {
    extern __shared__ uint32_t smem[];
    uint32_t* sAhi = smem;
    uint32_t* sAlo = smem + TILE_WORDS;
    uint32_t* sBhi = smem + 2 * TILE_WORDS;
    uint32_t* sBlo = smem + 3 * TILE_WORDS;

    int rowBase = blockIdx.x * 128;
    int tid = threadIdx.x;
    int wid = tid >> 5;
    int lane = tid & 31;
    int warpM = wid & 3;
    int warpN = wid >> 2;
    int g = lane >> 2;
    int tig = lane & 3;

    float acc[2][8][4];
    #pragma unroll
    for (int mt = 0; mt < 2; mt++)
        #pragma unroll
        for (int nt = 0; nt < 8; nt++)
            #pragma unroll
            for (int c = 0; c < 4; c++) acc[mt][nt][c] = 0.f;

    for (int chunk = 0; chunk < RELS; chunk++) {
        const float* Wr = W + (size_t)chunk * F * F;
        // A chunk: AGG rows rowBase..+127, k in [chunk*128, +128)
        for (int idx = tid; idx < 128 * 64; idx += 256) {
            int row = idx >> 6;
            int pair = idx & 63;
            int grow = rowBase + row;
            float2 v = make_float2(0.f, 0.f);
            if (grow < Nn)
                v = *(const float2*)(g_AGG + (size_t)grow * KTOT + chunk * F + pair * 2);
            sAhi[row * APITCH + pair] = pack_split_hi(v.x, v.y);
            sAlo[row * APITCH + pair] = pack_split_lo(v.x, v.y);
        }
        // B chunk: Bs[n][k] = W_chunk[k][n]
        for (int idx = tid; idx < 64 * 128; idx += 256) {
            int p = idx >> 7;
            int o = idx & 127;
            float vx = Wr[(size_t)(2 * p) * F + o];
            float vy = Wr[(size_t)(2 * p + 1) * F + o];
            sBhi[o * APITCH + p] = pack_split_hi(vx, vy);
            sBlo[o * APITCH + p] = pack_split_lo(vx, vy);
        }
        __syncthreads();

        #pragma unroll
        for (int split = 0; split < 3; split++) {
            const uint32_t* As = (split == 2) ? sAlo : sAhi;
            const uint32_t* Bs = (split == 1) ? sBlo : sBhi;
            #pragma unroll
            for (int ks = 0; ks < 8; ks++) {
                int kp = ks * 8 + tig;
                uint32_t a[2][4];
                #pragma unroll
                for (int mt = 0; mt < 2; mt++) {
                    int row = warpM * 32 + mt * 16;
                    a[mt][0] = As[(row + g) * APITCH + kp];
                    a[mt][1] = As[(row + g + 8) * APITCH + kp];
                    a[mt][2] = As[(row + g) * APITCH + kp + 4];
                    a[mt][3] = As[(row + g + 8) * APITCH + kp + 4];
                }
                uint32_t b[8][2];
                #pragma unroll
                for (int nt = 0; nt < 8; nt++) {
                    int n = warpN * 64 + nt * 8 + g;
                    b[nt][0] = Bs[n * APITCH + kp];
                    b[nt][1] = Bs[n * APITCH + kp + 4];
                }
                #pragma unroll
                for (int mt = 0; mt < 2; mt++)
                    #pragma unroll
                    for (int nt = 0; nt < 8; nt++)
                        mma16816(acc[mt][nt], a[mt], b[nt]);
            }
        }
        __syncthreads();
    }

    // ---- epilogue: bias (+relu), direct global stores ----
    #pragma unroll
    for (int mt = 0; mt < 2; mt++) {
        int row0 = rowBase + warpM * 32 + mt * 16 + g;
        int row1 = row0 + 8;
        #pragma unroll
        for (int nt = 0; nt < 8; nt++) {
            int col = warpN * 64 + nt * 8 + tig * 2;
            float b0 = __ldg(bias + col);
            float b1 = __ldg(bias + col + 1);
            float v0 = acc[mt][nt][0] + b0;
            float v1 = acc[mt][nt][1] + b1;
            float v2 = acc[mt][nt][2] + b0;
            float v3 = acc[mt][nt][3] + b1;
            if (relu) {
                v0 = v0 > 0.f ? v0 : 0.f;
                v1 = v1 > 0.f ? v1 : 0.f;
                v2 = v2 > 0.f ? v2 : 0.f;
                v3 = v3 > 0.f ? v3 : 0.f;
            }
            if (row0 < Nn) *(float2*)(outp + (size_t)row0 * F + col) = make_float2(v0, v1);
            if (row1 < Nn) *(float2*)(outp + (size_t)row1 * F + col) = make_float2(v2, v3);
        }
    }
}

// ---------------- launch ----------------
extern "C" void kernel_launch(void* const* d_in, const int* in_sizes, int n_in,
                              void* d_out, int out_size) {
    const float* x   = (const float*)d_in[0];
    const int*   ei  = (const int*)d_in[1];
    const int*   et  = (const int*)d_in[2];
    const float* ea  = (const float*)d_in[3];
    const float* w1  = (const float*)d_in[4];
    const float* q1  = (const float*)d_in[5];
    const float* k1  = (const float*)d_in[6];
    const float* e1  = (const float*)d_in[7];
    const float* we1 = (const float*)d_in[8];
    const float* b1  = (const float*)d_in[9];
    const float* w2  = (const float*)d_in[10];
    const float* q2  = (const float*)d_in[11];
    const float* k2  = (const float*)d_in[12];
    const float* e2  = (const float*)d_in[13];
    const float* we2 = (const float*)d_in[14];
    const float* b2  = (const float*)d_in[15];

    int Nn = in_sizes[0] / F;
    int Ecnt = in_sizes[2];
    const int* srcp = ei;
    const int* dstp = ei + Ecnt;
    float* outp = (float*)d_out;

    int nodeBlocks  = (Nn + 255) / 256;
    int edgeBlocks  = (Ecnt + 255) / 256;
    int scanBlocks  = (Nn + 255) / 256;
    int gemmBlocks  = (Nn + 127) / 128;
    int nqnkBlocks  = (Nn + 7) / 8;
    int warpNodeBlk = (Nn + 7) / 8;

    cudaFuncSetAttribute(gemm_mma_kernel, cudaFuncAttributeMaxDynamicSharedMemorySize,
                         GEMM_SMEM_TOTAL);

    void* hptr = nullptr;
    cudaGetSymbolAddress(&hptr, g_H);

    prep_kernel<<<(4 * RELS * F + 2 + 255) / 256, 256>>>(w1, q1, k1, w2, q2, k2,
                                                         we1, e1, we2, e2);

    // ----- CSR build (once; reused by both layers) -----
    zero_cnt_kernel<<<nodeBlocks, 256>>>(Nn);
    hist_kernel<<<edgeBlocks, 256>>>(dstp, Ecnt);
    scan1_kernel<<<scanBlocks, 256>>>(Nn);
    scan2_kernel<<<1, 1024>>>(scanBlocks);
    scan3_kernel<<<(Nn + 256) / 256, 256>>>(Nn, Ecnt);
    scatter_kernel<<<edgeBlocks, 256>>>(srcp, dstp, et, ea, Ecnt);

    // ----- layer 1: attn(x) -> AGG -> GEMM(+bias,relu) -> g_H -----
    nqnk_kernel<<<nqnkBlocks, 256>>>(x, 0, 0, Nn);
    fused_agg_kernel<<<warpNodeBlk, 256>>>(x, 0, 0, Nn);
    gemm_mma_kernel<<<gemmBlocks, 256, GEMM_SMEM_TOTAL>>>(w1, b1, (float*)hptr, 1, Nn);

    // ----- layer 2: attn(h) -> AGG -> GEMM(+bias) -> out -----
    nqnk_kernel<<<nqnkBlocks, 256>>>(x, 1, 1, Nn);
    fused_agg_kernel<<<warpNodeBlk, 256>>>(x, 1, 1, Nn);
    gemm_mma_kernel<<<gemmBlocks, 256, GEMM_SMEM_TOTAL>>>(w2, b2, outp, 0, Nn);

    (void)n_in; (void)out_size;
}

// round 7
// speedup vs baseline: 1.1097x; 1.1097x over previous
#include <cuda_runtime.h>
#include <cuda_bf16.h>
#include <cstdint>

#define RELS 3
#define F 128
#define NMAX 50000
#define EMAX 800000

// ---------------- scratch (static device globals; no allocation) ----------------
__device__ float    g_XW[(size_t)RELS * NMAX * F];   // [r][n][f]  76.8 MB
__device__ float    g_H[(size_t)NMAX * F];           // layer-1 output
__device__ uint32_t g_XHI[(size_t)NMAX * 64];        // bf16x2 pairs, hi part
__device__ uint32_t g_XLO[(size_t)NMAX * 64];        // bf16x2 pairs, lo part
__device__ uint32_t g_WHI[2 * RELS * 128 * 64];      // W^T split hi: [layer][r][n][kpair]
__device__ uint32_t g_WLO[2 * RELS * 128 * 64];
__device__ float    g_NQ[NMAX * RELS];
__device__ float    g_NK[NMAX * RELS];
__device__ float    g_EX[EMAX];
__device__ float    g_WQ[2 * RELS * F];
__device__ float    g_WK[2 * RELS * F];
__device__ float    g_CE[2];
// CSR scratch
__device__ int   g_CNT[NMAX];
__device__ int   g_ROWPTR[NMAX + 1];
__device__ int   g_PART[NMAX];
__device__ int   g_BSUM[1024];
__device__ int   g_NKIDX[EMAX];                      // sorted: src*RELS + et
__device__ int   g_ROWIDX[EMAX];                     // sorted: et*Nn + src
__device__ float g_SEA[EMAX];                        // sorted: edge_attr

__device__ __forceinline__ uint32_t pack_split_hi(float x, float y) {
    __nv_bfloat16 hx = __float2bfloat16_rn(x);
    __nv_bfloat16 hy = __float2bfloat16_rn(y);
    return ((uint32_t)*(uint16_t*)&hy << 16) | (uint32_t)*(uint16_t*)&hx;
}
__device__ __forceinline__ uint32_t pack_split_lo(float x, float y) {
    __nv_bfloat16 hx = __float2bfloat16_rn(x);
    __nv_bfloat16 hy = __float2bfloat16_rn(y);
    __nv_bfloat16 lx = __float2bfloat16_rn(x - __bfloat162float(hx));
    __nv_bfloat16 ly = __float2bfloat16_rn(y - __bfloat162float(hy));
    return ((uint32_t)*(uint16_t*)&ly << 16) | (uint32_t)*(uint16_t*)&lx;
}

// ---------------- prep: wq/wk vectors + edge scalar ----------------
__global__ void prep_kernel(const float* __restrict__ w1, const float* __restrict__ q1,
                            const float* __restrict__ k1,
                            const float* __restrict__ w2, const float* __restrict__ q2,
                            const float* __restrict__ k2,
                            const float* __restrict__ we1, const float* __restrict__ e1,
                            const float* __restrict__ we2, const float* __restrict__ e2) {
    int idx = blockIdx.x * blockDim.x + threadIdx.x;
    if (idx < 4 * RELS * F) {
        int which = idx / (RELS * F);
        int rem   = idx % (RELS * F);
        const float* w = (which < 2) ? w1 : w2;
        const float* v = (which == 0) ? q1 : (which == 1) ? k1 : (which == 2) ? q2 : k2;
        const float* row = w + (size_t)rem * F;
        float s = 0.f;
        #pragma unroll 8
        for (int o = 0; o < F; o++) s += row[o] * v[o];
        float* d = (which == 0) ? g_WQ
                 : (which == 1) ? g_WK
                 : (which == 2) ? (g_WQ + RELS * F)
                 : (g_WK + RELS * F);
        d[rem] = s;
    } else if (idx == 4 * RELS * F) {
        float s = 0.f;
        for (int o = 0; o < F; o++) s += we1[o] * e1[o];
        g_CE[0] = s;
    } else if (idx == 4 * RELS * F + 1) {
        float s = 0.f;
        for (int o = 0; o < F; o++) s += we2[o] * e2[o];
        g_CE[1] = s;
    }
}

// ---------------- prepw: split W (transposed) to bf16 hi/lo once ----------------
// layout: g_WHI[((layer*RELS + r)*128 + n)*64 + p] = pack(W[r][2p][n], W[r][2p+1][n])
__global__ void prepw_kernel(const float* __restrict__ w1, const float* __restrict__ w2) {
    int idx = blockIdx.x * blockDim.x + threadIdx.x;   // total 2*3*64*128
    if (idx >= 2 * RELS * 64 * 128) return;
    int n     = idx & 127;
    int p     = (idx >> 7) & 63;
    int r     = (idx >> 13) % RELS;
    int layer = idx / (RELS * 64 * 128);
    const float* W = (layer == 0) ? w1 : w2;
    const float* Wr = W + (size_t)r * F * F;
    float vx = Wr[(size_t)(2 * p) * F + n];
    float vy = Wr[(size_t)(2 * p + 1) * F + n];
    size_t o = ((size_t)(layer * RELS + r) * 128 + n) * 64 + p;
    g_WHI[o] = pack_split_hi(vx, vy);
    g_WLO[o] = pack_split_lo(vx, vy);
}

// ---------------- CSR build ----------------
__global__ void zero_cnt_kernel(int Nn) {
    int i = blockIdx.x * blockDim.x + threadIdx.x;
    if (i < Nn) g_CNT[i] = 0;
}
__global__ void hist_kernel(const int* __restrict__ dst, int Ecnt) {
    int e = blockIdx.x * blockDim.x + threadIdx.x;
    if (e < Ecnt) atomicAdd(&g_CNT[dst[e]], 1);
}
__global__ void scan1_kernel(int Nn) {
    __shared__ int sh[256];
    int i = blockIdx.x * 256 + threadIdx.x;
    int v = (i < Nn) ? g_CNT[i] : 0;
    sh[threadIdx.x] = v;
    __syncthreads();
    #pragma unroll
    for (int off = 1; off < 256; off <<= 1) {
        int t = (threadIdx.x >= off) ? sh[threadIdx.x - off] : 0;
        __syncthreads();
        sh[threadIdx.x] += t;
        __syncthreads();
    }
    if (i < Nn) g_PART[i] = sh[threadIdx.x] - v;
    if (threadIdx.x == 255) g_BSUM[blockIdx.x] = sh[255];
}
__global__ void scan2_kernel(int nb) {
    __shared__ int sh[1024];
    int v = (threadIdx.x < nb) ? g_BSUM[threadIdx.x] : 0;
    sh[threadIdx.x] = v;
    __syncthreads();
    #pragma unroll
    for (int off = 1; off < 1024; off <<= 1) {
        int t = (threadIdx.x >= off) ? sh[threadIdx.x - off] : 0;
        __syncthreads();
        sh[threadIdx.x] += t;
        __syncthreads();
    }
    if (threadIdx.x < nb) g_BSUM[threadIdx.x] = sh[threadIdx.x] - v;
}
__global__ void scan3_kernel(int Nn, int Ecnt) {
    int i = blockIdx.x * blockDim.x + threadIdx.x;
    if (i < Nn) {
        g_ROWPTR[i] = g_PART[i] + g_BSUM[i >> 8];
        g_CNT[i] = 0;
    }
    if (i == Nn) g_ROWPTR[Nn] = Ecnt;
}
__global__ void scatter_kernel(const int* __restrict__ src, const int* __restrict__ dst,
                               const int* __restrict__ et, const float* __restrict__ ea,
                               int Ecnt, int Nn) {
    int e = blockIdx.x * blockDim.x + threadIdx.x;
    if (e >= Ecnt) return;
    int d = dst[e];
    int pos = g_ROWPTR[d] + atomicAdd(&g_CNT[d], 1);
    int s = src[e], t = et[e];
    g_NKIDX[pos]  = s * RELS + t;
    g_ROWIDX[pos] = t * Nn + s;
    g_SEA[pos]    = ea[e];
}

// ------- fused: X (or H) -> bf16 hi/lo split + attention logits; warp per node -------
__global__ __launch_bounds__(256) void split_nqnk_kernel(const float* __restrict__ xin,
                                                         int use_h, int layer, int Nn) {
    __shared__ float swq[RELS * F];
    __shared__ float swk[RELS * F];
    const float* X = use_h ? g_H : xin;
    const float* WQ = g_WQ + layer * RELS * F;
    const float* WK = g_WK + layer * RELS * F;
    for (int i = threadIdx.x; i < RELS * F; i += blockDim.x) {
        swq[i] = WQ[i];
        swk[i] = WK[i];
    }
    __syncthreads();

    int warp = (blockIdx.x * blockDim.x + threadIdx.x) >> 5;
    int lane = threadIdx.x & 31;
    if (warp >= Nn) return;

    float4 v = ((const float4*)(X + (size_t)warp * F))[lane];   // elems 4l..4l+3

    // split + store packed pairs (2 pairs per lane)
    uint32_t* xh = g_XHI + (size_t)warp * 64;
    uint32_t* xl = g_XLO + (size_t)warp * 64;
    xh[lane * 2]     = pack_split_hi(v.x, v.y);
    xh[lane * 2 + 1] = pack_split_hi(v.z, v.w);
    xl[lane * 2]     = pack_split_lo(v.x, v.y);
    xl[lane * 2 + 1] = pack_split_lo(v.z, v.w);

    // attention logits
    #pragma unroll
    for (int r = 0; r < RELS; r++) {
        const float4 q4 = ((const float4*)(swq + r * F))[lane];
        const float4 k4 = ((const float4*)(swk + r * F))[lane];
        float sq = v.x * q4.x + v.y * q4.y + v.z * q4.z + v.w * q4.w;
        float sk = v.x * k4.x + v.y * k4.y + v.z * k4.z + v.w * k4.w;
        #pragma unroll
        for (int off = 16; off; off >>= 1) {
            sq += __shfl_down_sync(0xffffffffu, sq, off);
            sk += __shfl_down_sync(0xffffffffu, sk, off);
        }
        if (lane == 0) {
            g_NQ[warp * RELS + r] = sq;
            g_NK[warp * RELS + r] = sk;
        }
    }
}

// ============== mma.sync bf16 GEMM (pre-split operands): XW[r] = X @ W_r ==============
#define APITCH 68
#define TILE_WORDS (128 * APITCH)
#define GEMM_SMEM_TOTAL (4 * TILE_WORDS * 4)

__device__ __forceinline__ void mma16816(float* d, const uint32_t* a, const uint32_t* b) {
    asm volatile("mma.sync.aligned.m16n8k16.row.col.f32.bf16.bf16.f32 "
                 "{%0,%1,%2,%3}, {%4,%5,%6,%7}, {%8,%9}, {%0,%1,%2,%3};"
                 : "+f"(d[0]), "+f"(d[1]), "+f"(d[2]), "+f"(d[3])
                 : "r"(a[0]), "r"(a[1]), "r"(a[2]), "r"(a[3]), "r"(b[0]), "r"(b[1]));
}

__global__ __launch_bounds__(256) void gemm_mma_kernel(int layer, int Nn) {
    extern __shared__ uint32_t smem[];
    uint32_t* sAhi = smem;
    uint32_t* sAlo = smem + TILE_WORDS;
    uint32_t* sBhi = smem + 2 * TILE_WORDS;
    uint32_t* sBlo = smem + 3 * TILE_WORDS;

    int r = blockIdx.y;
    float* outp = g_XW + (size_t)r * Nn * F;
    int rowBase = blockIdx.x * 128;
    int tid = threadIdx.x;

    // ---- A tiles: copy pre-split pairs ----
    for (int idx = tid; idx < 128 * 64; idx += 256) {
        int row = idx >> 6;
        int pair = idx & 63;
        int grow = rowBase + row;
        uint32_t hi = 0, lo = 0;
        if (grow < Nn) {
            hi = g_XHI[(size_t)grow * 64 + pair];
            lo = g_XLO[(size_t)grow * 64 + pair];
        }
        sAhi[row * APITCH + pair] = hi;
        sAlo[row * APITCH + pair] = lo;
    }
    // ---- B tiles: copy pre-split transposed weights ----
    {
        const uint32_t* wh = g_WHI + (size_t)(layer * RELS + r) * 128 * 64;
        const uint32_t* wl = g_WLO + (size_t)(layer * RELS + r) * 128 * 64;
        for (int idx = tid; idx < 128 * 64; idx += 256) {
            int n = idx >> 6;
            int p = idx & 63;
            sBhi[n * APITCH + p] = wh[idx];
            sBlo[n * APITCH + p] = wl[idx];
        }
    }
    __syncthreads();

    int wid = tid >> 5;
    int lane = tid & 31;
    int warpM = wid & 3;
    int warpN = wid >> 2;
    int g = lane >> 2;
    int tig = lane & 3;

    float acc[2][8][4];
    #pragma unroll
    for (int mt = 0; mt < 2; mt++)
        #pragma unroll
        for (int nt = 0; nt < 8; nt++)
            #pragma unroll
            for (int c = 0; c < 4; c++) acc[mt][nt][c] = 0.f;

    #pragma unroll
    for (int split = 0; split < 3; split++) {
        const uint32_t* As = (split == 2) ? sAlo : sAhi;
        const uint32_t* Bs = (split == 1) ? sBlo : sBhi;
        #pragma unroll
        for (int ks = 0; ks < 8; ks++) {
            int kp = ks * 8 + tig;
            uint32_t a[2][4];
            #pragma unroll
            for (int mt = 0; mt < 2; mt++) {
                int row = warpM * 32 + mt * 16;
                a[mt][0] = As[(row + g) * APITCH + kp];
                a[mt][1] = As[(row + g + 8) * APITCH + kp];
                a[mt][2] = As[(row + g) * APITCH + kp + 4];
                a[mt][3] = As[(row + g + 8) * APITCH + kp + 4];
            }
            uint32_t b[8][2];
            #pragma unroll
            for (int nt = 0; nt < 8; nt++) {
                int n = warpN * 64 + nt * 8 + g;
                b[nt][0] = Bs[n * APITCH + kp];
                b[nt][1] = Bs[n * APITCH + kp + 4];
            }
            #pragma unroll
            for (int mt = 0; mt < 2; mt++)
                #pragma unroll
                for (int nt = 0; nt < 8; nt++)
                    mma16816(acc[mt][nt], a[mt], b[nt]);
        }
    }

    #pragma unroll
    for (int mt = 0; mt < 2; mt++) {
        int row0 = rowBase + warpM * 32 + mt * 16 + g;
        int row1 = row0 + 8;
        #pragma unroll
        for (int nt = 0; nt < 8; nt++) {
            int col = warpN * 64 + nt * 8 + tig * 2;
            if (row0 < Nn)
                *(float2*)(outp + (size_t)row0 * F + col) = make_float2(acc[mt][nt][0], acc[mt][nt][1]);
            if (row1 < Nn)
                *(float2*)(outp + (size_t)row1 * F + col) = make_float2(acc[mt][nt][2], acc[mt][nt][3]);
        }
    }
}

// ---------------- fused softmax + aggregate + bias(+relu), warp per dst node ----------------
__global__ __launch_bounds__(256) void fused_agg_kernel(float* __restrict__ outp,
                                                        const float* __restrict__ bias,
                                                        int layer, int relu, int Nn) {
    int node = (blockIdx.x * blockDim.x + threadIdx.x) >> 5;
    int lane = threadIdx.x & 31;
    if (node >= Nn) return;

    int start = g_ROWPTR[node];
    int end   = g_ROWPTR[node + 1];
    float ce  = g_CE[layer];
    float nq0 = g_NQ[node * RELS + 0];
    float nq1 = g_NQ[node * RELS + 1];
    float nq2 = g_NQ[node * RELS + 2];

    float denom = 0.f;
    for (int i = start + lane; i < end; i += 32) {
        int nkidx = g_NKIDX[i];
        int t = nkidx - (nkidx / RELS) * RELS;
        float nq = (t == 0) ? nq0 : (t == 1) ? nq1 : nq2;
        float a = nq + g_NK[nkidx] + ce * g_SEA[i];
        a = (a > 0.f) ? a : 0.2f * a;
        float ex = expf(a);
        g_EX[i] = ex;
        denom += ex;
    }
    #pragma unroll
    for (int off = 16; off; off >>= 1)
        denom += __shfl_xor_sync(0xffffffffu, denom, off);
    float inv = 1.f / (denom + 1e-16f);

    float4 acc = make_float4(0.f, 0.f, 0.f, 0.f);
    int i = start;
    for (; i + 1 < end; i += 2) {
        float at0 = g_EX[i] * inv;
        float at1 = g_EX[i + 1] * inv;
        const float4* r0 = (const float4*)(g_XW + (size_t)g_ROWIDX[i] * F);
        const float4* r1 = (const float4*)(g_XW + (size_t)g_ROWIDX[i + 1] * F);
        float4 v0 = r0[lane];
        float4 v1 = r1[lane];
        acc.x += at0 * v0.x + at1 * v1.x;
        acc.y += at0 * v0.y + at1 * v1.y;
        acc.z += at0 * v0.z + at1 * v1.z;
        acc.w += at0 * v0.w + at1 * v1.w;
    }
    if (i < end) {
        float at = g_EX[i] * inv;
        const float4* r0 = (const float4*)(g_XW + (size_t)g_ROWIDX[i] * F);
        float4 v = r0[lane];
        acc.x += at * v.x;
        acc.y += at * v.y;
        acc.z += at * v.z;
        acc.w += at * v.w;
    }

    const float4 b = *(const float4*)(bias + lane * 4);
    acc.x += b.x; acc.y += b.y; acc.z += b.z; acc.w += b.w;
    if (relu) {
        acc.x = acc.x > 0.f ? acc.x : 0.f;
        acc.y = acc.y > 0.f ? acc.y : 0.f;
        acc.z = acc.z > 0.f ? acc.z : 0.f;
        acc.w = acc.w > 0.f ? acc.w : 0.f;
    }
    *(float4*)(outp + (size_t)node * F + lane * 4) = acc;
}

// ---------------- launch ----------------
extern "C" void kernel_launch(void* const* d_in, const int* in_sizes, int n_in,
                              void* d_out, int out_size) {
    const float* x   = (const float*)d_in[0];
    const int*   ei  = (const int*)d_in[1];
    const int*   et  = (const int*)d_in[2];
    const float* ea  = (const float*)d_in[3];
    const float* w1  = (const float*)d_in[4];
    const float* q1  = (const float*)d_in[5];
    const float* k1  = (const float*)d_in[6];
    const float* e1  = (const float*)d_in[7];
    const float* we1 = (const float*)d_in[8];
    const float* b1  = (const float*)d_in[9];
    const float* w2  = (const float*)d_in[10];
    const float* q2  = (const float*)d_in[11];
    const float* k2  = (const float*)d_in[12];
    const float* e2  = (const float*)d_in[13];
    const float* we2 = (const float*)d_in[14];
    const float* b2  = (const float*)d_in[15];

    int Nn = in_sizes[0] / F;
    int Ecnt = in_sizes[2];
    const int* srcp = ei;
    const int* dstp = ei + Ecnt;
    float* outp = (float*)d_out;

    int nodeBlocks  = (Nn + 255) / 256;
    int edgeBlocks  = (Ecnt + 255) / 256;
    int scanBlocks  = (Nn + 255) / 256;
    dim3 gemmGrid((Nn + 127) / 128, RELS);
    int warpNodeBlk = (Nn + 7) / 8;

    cudaFuncSetAttribute(gemm_mma_kernel, cudaFuncAttributeMaxDynamicSharedMemorySize,
                         GEMM_SMEM_TOTAL);

    void* hptr = nullptr;
    cudaGetSymbolAddress(&hptr, g_H);

    prep_kernel<<<(4 * RELS * F + 2 + 255) / 256, 256>>>(w1, q1, k1, w2, q2, k2,
                                                         we1, e1, we2, e2);
    prepw_kernel<<<(2 * RELS * 64 * 128 + 255) / 256, 256>>>(w1, w2);

    // ----- CSR build (once; reused by both layers) -----
    zero_cnt_kernel<<<nodeBlocks, 256>>>(Nn);
    hist_kernel<<<edgeBlocks, 256>>>(dstp, Ecnt);
    scan1_kernel<<<scanBlocks, 256>>>(Nn);
    scan2_kernel<<<1, 1024>>>(scanBlocks);
    scan3_kernel<<<(Nn + 256) / 256, 256>>>(Nn, Ecnt);
    scatter_kernel<<<edgeBlocks, 256>>>(srcp, dstp, et, ea, Ecnt, Nn);

    // ----- layer 1 -----
    split_nqnk_kernel<<<warpNodeBlk, 256>>>(x, 0, 0, Nn);
    gemm_mma_kernel<<<gemmGrid, 256, GEMM_SMEM_TOTAL>>>(0, Nn);
    fused_agg_kernel<<<warpNodeBlk, 256>>>((float*)hptr, b1, 0, 1, Nn);

    // ----- layer 2 -----
    split_nqnk_kernel<<<warpNodeBlk, 256>>>(x, 1, 1, Nn);
    gemm_mma_kernel<<<gemmGrid, 256, GEMM_SMEM_TOTAL>>>(1, Nn);
    fused_agg_kernel<<<warpNodeBlk, 256>>>(outp, b2, 1, 0, Nn);

    (void)n_in; (void)out_size;
}

// round 9
// speedup vs baseline: 1.1377x; 1.0252x over previous
#include <cuda_runtime.h>
#include <cuda_bf16.h>
#include <cstdint>

#define RELS 3
#define F 128
#define NMAX 50000
#define EMAX 800000

// ---------------- scratch (static device globals; no allocation) ----------------
__device__ float    g_XW[(size_t)RELS * NMAX * F];   // [r][n][f]  76.8 MB
__device__ float    g_H[(size_t)NMAX * F];           // layer-1 output
__device__ uint32_t g_XHI[(size_t)NMAX * 64];        // bf16x2 pairs, hi part
__device__ uint32_t g_XLO[(size_t)NMAX * 64];        // bf16x2 pairs, lo part
__device__ uint32_t g_WHI[2 * RELS * 128 * 64];      // W^T split hi: [layer][r][n][kpair]
__device__ uint32_t g_WLO[2 * RELS * 128 * 64];
__device__ float    g_NQ[NMAX * RELS];               // layer-1 logits
__device__ float    g_NK[NMAX * RELS];
__device__ float    g_NQ2[NMAX * RELS];              // layer-2 logits (written by L1 agg tail)
__device__ float    g_NK2[NMAX * RELS];
__device__ float    g_EX[EMAX];
__device__ float    g_WQ[2 * RELS * F];
__device__ float    g_WK[2 * RELS * F];
__device__ float    g_CE[2];
// CSR scratch
__device__ int   g_CNT[NMAX];
__device__ int   g_ROWPTR[NMAX + 1];
__device__ int   g_PART[NMAX];
__device__ int   g_BSUM[1024];
__device__ int4  g_EDGE[EMAX];                       // {nkidx, rowidx, sea_bits, 0}

__device__ __forceinline__ uint32_t pack_split_hi(float x, float y) {
    __nv_bfloat16 hx = __float2bfloat16_rn(x);
    __nv_bfloat16 hy = __float2bfloat16_rn(y);
    return ((uint32_t)*(uint16_t*)&hy << 16) | (uint32_t)*(uint16_t*)&hx;
}
__device__ __forceinline__ uint32_t pack_split_lo(float x, float y) {
    __nv_bfloat16 hx = __float2bfloat16_rn(x);
    __nv_bfloat16 hy = __float2bfloat16_rn(y);
    __nv_bfloat16 lx = __float2bfloat16_rn(x - __bfloat162float(hx));
    __nv_bfloat16 ly = __float2bfloat16_rn(y - __bfloat162float(hy));
    return ((uint32_t)*(uint16_t*)&ly << 16) | (uint32_t)*(uint16_t*)&lx;
}

// ---------------- prep: wq/wk vectors + edge scalar ----------------
__global__ void prep_kernel(const float* __restrict__ w1, const float* __restrict__ q1,
                            const float* __restrict__ k1,
                            const float* __restrict__ w2, const float* __restrict__ q2,
                            const float* __restrict__ k2,
                            const float* __restrict__ we1, const float* __restrict__ e1,
                            const float* __restrict__ we2, const float* __restrict__ e2) {
    int idx = blockIdx.x * blockDim.x + threadIdx.x;
    if (idx < 4 * RELS * F) {
        int which = idx / (RELS * F);
        int rem   = idx % (RELS * F);
        const float* w = (which < 2) ? w1 : w2;
        const float* v = (which == 0) ? q1 : (which == 1) ? k1 : (which == 2) ? q2 : k2;
        const float* row = w + (size_t)rem * F;
        float s = 0.f;
        #pragma unroll 8
        for (int o = 0; o < F; o++) s += row[o] * v[o];
        float* d = (which == 0) ? g_WQ
                 : (which == 1) ? g_WK
                 : (which == 2) ? (g_WQ + RELS * F)
                 : (g_WK + RELS * F);
        d[rem] = s;
    } else if (idx == 4 * RELS * F) {
        float s = 0.f;
        for (int o = 0; o < F; o++) s += we1[o] * e1[o];
        g_CE[0] = s;
    } else if (idx == 4 * RELS * F + 1) {
        float s = 0.f;
        for (int o = 0; o < F; o++) s += we2[o] * e2[o];
        g_CE[1] = s;
    }
}

// ---------------- prepw: split W (transposed) to bf16 hi/lo once ----------------
__global__ void prepw_kernel(const float* __restrict__ w1, const float* __restrict__ w2) {
    int idx = blockIdx.x * blockDim.x + threadIdx.x;   // total 2*3*64*128
    if (idx >= 2 * RELS * 64 * 128) return;
    int n     = idx & 127;
    int p     = (idx >> 7) & 63;
    int r     = (idx >> 13) % RELS;
    int layer = idx / (RELS * 64 * 128);
    const float* W = (layer == 0) ? w1 : w2;
    const float* Wr = W + (size_t)r * F * F;
    float vx = Wr[(size_t)(2 * p) * F + n];
    float vy = Wr[(size_t)(2 * p + 1) * F + n];
    size_t o = ((size_t)(layer * RELS + r) * 128 + n) * 64 + p;
    g_WHI[o] = pack_split_hi(vx, vy);
    g_WLO[o] = pack_split_lo(vx, vy);
}

// ---------------- CSR build ----------------
__global__ void zero_cnt_kernel(int Nn) {
    int i = blockIdx.x * blockDim.x + threadIdx.x;
    if (i < Nn) g_CNT[i] = 0;
}
__global__ void hist_kernel(const int* __restrict__ dst, int Ecnt) {
    int e = blockIdx.x * blockDim.x + threadIdx.x;
    if (e < Ecnt) atomicAdd(&g_CNT[dst[e]], 1);
}
__global__ void scan1_kernel(int Nn) {
    __shared__ int sh[256];
    int i = blockIdx.x * 256 + threadIdx.x;
    int v = (i < Nn) ? g_CNT[i] : 0;
    sh[threadIdx.x] = v;
    __syncthreads();
    #pragma unroll
    for (int off = 1; off < 256; off <<= 1) {
        int t = (threadIdx.x >= off) ? sh[threadIdx.x - off] : 0;
        __syncthreads();
        sh[threadIdx.x] += t;
        __syncthreads();
    }
    if (i < Nn) g_PART[i] = sh[threadIdx.x] - v;
    if (threadIdx.x == 255) g_BSUM[blockIdx.x] = sh[255];
}
__global__ void scan2_kernel(int nb) {
    __shared__ int sh[1024];
    int v = (threadIdx.x < nb) ? g_BSUM[threadIdx.x] : 0;
    sh[threadIdx.x] = v;
    __syncthreads();
    #pragma unroll
    for (int off = 1; off < 1024; off <<= 1) {
        int t = (threadIdx.x >= off) ? sh[threadIdx.x - off] : 0;
        __syncthreads();
        sh[threadIdx.x] += t;
        __syncthreads();
    }
    if (threadIdx.x < nb) g_BSUM[threadIdx.x] = sh[threadIdx.x] - v;
}
__global__ void scan3_kernel(int Nn, int Ecnt) {
    int i = blockIdx.x * blockDim.x + threadIdx.x;
    if (i < Nn) {
        g_ROWPTR[i] = g_PART[i] + g_BSUM[i >> 8];
        g_CNT[i] = 0;
    }
    if (i == Nn) g_ROWPTR[Nn] = Ecnt;
}
__global__ void scatter_kernel(const int* __restrict__ src, const int* __restrict__ dst,
                               const int* __restrict__ et, const float* __restrict__ ea,
                               int Ecnt, int Nn) {
    int e = blockIdx.x * blockDim.x + threadIdx.x;
    if (e >= Ecnt) return;
    int d = dst[e];
    int pos = g_ROWPTR[d] + atomicAdd(&g_CNT[d], 1);
    int s = src[e], t = et[e];
    g_EDGE[pos] = make_int4(s * RELS + t, t * Nn + s, __float_as_int(ea[e]), 0);
}

// ------- fused: x -> bf16 hi/lo split + layer-1 attention logits; warp per node -------
__global__ __launch_bounds__(256) void split_nqnk_kernel(const float* __restrict__ xin, int Nn) {
    __shared__ float swq[RELS * F];
    __shared__ float swk[RELS * F];
    for (int i = threadIdx.x; i < RELS * F; i += blockDim.x) {
        swq[i] = g_WQ[i];
        swk[i] = g_WK[i];
    }
    __syncthreads();

    int warp = (blockIdx.x * blockDim.x + threadIdx.x) >> 5;
    int lane = threadIdx.x & 31;
    if (warp >= Nn) return;

    float4 v = ((const float4*)(xin + (size_t)warp * F))[lane];

    uint32_t* xh = g_XHI + (size_t)warp * 64;
    uint32_t* xl = g_XLO + (size_t)warp * 64;
    xh[lane * 2]     = pack_split_hi(v.x, v.y);
    xh[lane * 2 + 1] = pack_split_hi(v.z, v.w);
    xl[lane * 2]     = pack_split_lo(v.x, v.y);
    xl[lane * 2 + 1] = pack_split_lo(v.z, v.w);

    #pragma unroll
    for (int r = 0; r < RELS; r++) {
        const float4 q4 = ((const float4*)(swq + r * F))[lane];
        const float4 k4 = ((const float4*)(swk + r * F))[lane];
        float sq = v.x * q4.x + v.y * q4.y + v.z * q4.z + v.w * q4.w;
        float sk = v.x * k4.x + v.y * k4.y + v.z * k4.z + v.w * k4.w;
        #pragma unroll
        for (int off = 16; off; off >>= 1) {
            sq += __shfl_down_sync(0xffffffffu, sq, off);
            sk += __shfl_down_sync(0xffffffffu, sk, off);
        }
        if (lane == 0) {
            g_NQ[warp * RELS + r] = sq;
            g_NK[warp * RELS + r] = sk;
        }
    }
}

// ============== mma.sync bf16 GEMM (pre-split operands): XW[r] = X @ W_r ==============
#define APITCH 68
#define TILE_WORDS (128 * APITCH)
#define GEMM_SMEM_TOTAL (4 * TILE_WORDS * 4)

__device__ __forceinline__ void mma16816(float* d, const uint32_t* a, const uint32_t* b) {
    asm volatile("mma.sync.aligned.m16n8k16.row.col.f32.bf16.bf16.f32 "
                 "{%0,%1,%2,%3}, {%4,%5,%6,%7}, {%8,%9}, {%0,%1,%2,%3};"
                 : "+f"(d[0]), "+f"(d[1]), "+f"(d[2]), "+f"(d[3])
                 : "r"(a[0]), "r"(a[1]), "r"(a[2]), "r"(a[3]), "r"(b[0]), "r"(b[1]));
}

__global__ __launch_bounds__(256) void gemm_mma_kernel(int layer, int Nn) {
    extern __shared__ uint32_t smem[];
    uint32_t* sAhi = smem;
    uint32_t* sAlo = smem + TILE_WORDS;
    uint32_t* sBhi = smem + 2 * TILE_WORDS;
    uint32_t* sBlo = smem + 3 * TILE_WORDS;

    int r = blockIdx.y;
    float* outp = g_XW + (size_t)r * Nn * F;
    int rowBase = blockIdx.x * 128;
    int tid = threadIdx.x;

    for (int idx = tid; idx < 128 * 64; idx += 256) {
        int row = idx >> 6;
        int pair = idx & 63;
        int grow = rowBase + row;
        uint32_t hi = 0, lo = 0;
        if (grow < Nn) {
            hi = g_XHI[(size_t)grow * 64 + pair];
            lo = g_XLO[(size_t)grow * 64 + pair];
        }
        sAhi[row * APITCH + pair] = hi;
        sAlo[row * APITCH + pair] = lo;
    }
    {
        const uint32_t* wh = g_WHI + (size_t)(layer * RELS + r) * 128 * 64;
        const uint32_t* wl = g_WLO + (size_t)(layer * RELS + r) * 128 * 64;
        for (int idx = tid; idx < 128 * 64; idx += 256) {
            int n = idx >> 6;
            int p = idx & 63;
            sBhi[n * APITCH + p] = wh[idx];
            sBlo[n * APITCH + p] = wl[idx];
        }
    }
    __syncthreads();

    int wid = tid >> 5;
    int lane = tid & 31;
    int warpM = wid & 3;
    int warpN = wid >> 2;
    int g = lane >> 2;
    int tig = lane & 3;

    float acc[2][8][4];
    #pragma unroll
    for (int mt = 0; mt < 2; mt++)
        #pragma unroll
        for (int nt = 0; nt < 8; nt++)
            #pragma unroll
            for (int c = 0; c < 4; c++) acc[mt][nt][c] = 0.f;

    #pragma unroll
    for (int split = 0; split < 3; split++) {
        const uint32_t* As = (split == 2) ? sAlo : sAhi;
        const uint32_t* Bs = (split == 1) ? sBlo : sBhi;
        #pragma unroll
        for (int ks = 0; ks < 8; ks++) {
            int kp = ks * 8 + tig;
            uint32_t a[2][4];
            #pragma unroll
            for (int mt = 0; mt < 2; mt++) {
                int row = warpM * 32 + mt * 16;
                a[mt][0] = As[(row + g) * APITCH + kp];
                a[mt][1] = As[(row + g + 8) * APITCH + kp];
                a[mt][2] = As[(row + g) * APITCH + kp + 4];
                a[mt][3] = As[(row + g + 8) * APITCH + kp + 4];
            }
            uint32_t b[8][2];
            #pragma unroll
            for (int nt = 0; nt < 8; nt++) {
                int n = warpN * 64 + nt * 8 + g;
                b[nt][0] = Bs[n * APITCH + kp];
                b[nt][1] = Bs[n * APITCH + kp + 4];
            }
            #pragma unroll
            for (int mt = 0; mt < 2; mt++)
                #pragma unroll
                for (int nt = 0; nt < 8; nt++)
                    mma16816(acc[mt][nt], a[mt], b[nt]);
        }
    }

    #pragma unroll
    for (int mt = 0; mt < 2; mt++) {
        int row0 = rowBase + warpM * 32 + mt * 16 + g;
        int row1 = row0 + 8;
        #pragma unroll
        for (int nt = 0; nt < 8; nt++) {
            int col = warpN * 64 + nt * 8 + tig * 2;
            if (row0 < Nn)
                *(float2*)(outp + (size_t)row0 * F + col) = make_float2(acc[mt][nt][0], acc[mt][nt][1]);
            if (row1 < Nn)
                *(float2*)(outp + (size_t)row1 * F + col) = make_float2(acc[mt][nt][2], acc[mt][nt][3]);
        }
    }
}

// -------- fused softmax + aggregate + bias(+relu) [+ next-layer split & logits] --------
// warp per dst node. Reads logits from (g_NQ,g_NK) or (g_NQ2,g_NK2) per `use2`;
// the donext tail writes ONLY to (g_NQ2,g_NK2) — no same-kernel aliasing.
__global__ __launch_bounds__(256) void fused_agg_kernel(float* __restrict__ outp,
                                                        const float* __restrict__ bias,
                                                        int layer, int relu, int donext,
                                                        int use2, int Nn) {
    __shared__ float swq[RELS * F];
    __shared__ float swk[RELS * F];
    if (donext) {
        const float* WQ = g_WQ + (layer + 1) * RELS * F;
        const float* WK = g_WK + (layer + 1) * RELS * F;
        for (int i = threadIdx.x; i < RELS * F; i += blockDim.x) {
            swq[i] = WQ[i];
            swk[i] = WK[i];
        }
        __syncthreads();
    }

    int node = (blockIdx.x * blockDim.x + threadIdx.x) >> 5;
    int lane = threadIdx.x & 31;
    if (node >= Nn) return;

    const float* NQ = use2 ? g_NQ2 : g_NQ;
    const float* NK = use2 ? g_NK2 : g_NK;

    int start = g_ROWPTR[node];
    int end   = g_ROWPTR[node + 1];
    float ce  = g_CE[layer];
    float nq0 = NQ[node * RELS + 0];
    float nq1 = NQ[node * RELS + 1];
    float nq2 = NQ[node * RELS + 2];

    // phase 1: lane-parallel exp + denominator (one coalesced int4 per lane)
    float denom = 0.f;
    for (int i = start + lane; i < end; i += 32) {
        int4 e = g_EDGE[i];
        int t = e.x - (e.x / RELS) * RELS;
        float nq = (t == 0) ? nq0 : (t == 1) ? nq1 : nq2;
        float a = nq + NK[e.x] + ce * __int_as_float(e.z);
        a = (a > 0.f) ? a : 0.2f * a;
        float ex = expf(a);
        g_EX[i] = ex;
        denom += ex;
    }
    #pragma unroll
    for (int off = 16; off; off >>= 1)
        denom += __shfl_xor_sync(0xffffffffu, denom, off);
    float inv = 1.f / (denom + 1e-16f);

    // phase 2: warp-per-edge gather, unroll 4 for MLP
    const int* epack = (const int*)g_EDGE;
    float4 acc = make_float4(0.f, 0.f, 0.f, 0.f);
    int i = start;
    for (; i + 3 < end; i += 4) {
        float at0 = g_EX[i] * inv;
        float at1 = g_EX[i + 1] * inv;
        float at2 = g_EX[i + 2] * inv;
        float at3 = g_EX[i + 3] * inv;
        int r0 = epack[4 * i + 1];
        int r1 = epack[4 * i + 5];
        int r2 = epack[4 * i + 9];
        int r3 = epack[4 * i + 13];
        float4 v0 = ((const float4*)(g_XW + (size_t)r0 * F))[lane];
        float4 v1 = ((const float4*)(g_XW + (size_t)r1 * F))[lane];
        float4 v2 = ((const float4*)(g_XW + (size_t)r2 * F))[lane];
        float4 v3 = ((const float4*)(g_XW + (size_t)r3 * F))[lane];
        acc.x += at0 * v0.x + at1 * v1.x + at2 * v2.x + at3 * v3.x;
        acc.y += at0 * v0.y + at1 * v1.y + at2 * v2.y + at3 * v3.y;
        acc.z += at0 * v0.z + at1 * v1.z + at2 * v2.z + at3 * v3.z;
        acc.w += at0 * v0.w + at1 * v1.w + at2 * v2.w + at3 * v3.w;
    }
    for (; i < end; i++) {
        float at = g_EX[i] * inv;
        int r0 = epack[4 * i + 1];
        float4 v = ((const float4*)(g_XW + (size_t)r0 * F))[lane];
        acc.x += at * v.x;
        acc.y += at * v.y;
        acc.z += at * v.z;
        acc.w += at * v.w;
    }

    const float4 b = *(const float4*)(bias + lane * 4);
    acc.x += b.x; acc.y += b.y; acc.z += b.z; acc.w += b.w;
    if (relu) {
        acc.x = acc.x > 0.f ? acc.x : 0.f;
        acc.y = acc.y > 0.f ? acc.y : 0.f;
        acc.z = acc.z > 0.f ? acc.z : 0.f;
        acc.w = acc.w > 0.f ? acc.w : 0.f;
    }
    *(float4*)(outp + (size_t)node * F + lane * 4) = acc;

    // fused tail: bf16 split + next-layer logits on the h row; writes NQ2/NK2 only
    if (donext) {
        uint32_t* xh = g_XHI + (size_t)node * 64;
        uint32_t* xl = g_XLO + (size_t)node * 64;
        xh[lane * 2]     = pack_split_hi(acc.x, acc.y);
        xh[lane * 2 + 1] = pack_split_hi(acc.z, acc.w);
        xl[lane * 2]     = pack_split_lo(acc.x, acc.y);
        xl[lane * 2 + 1] = pack_split_lo(acc.z, acc.w);

        #pragma unroll
        for (int r = 0; r < RELS; r++) {
            const float4 q4 = ((const float4*)(swq + r * F))[lane];
            const float4 k4 = ((const float4*)(swk + r * F))[lane];
            float sq = acc.x * q4.x + acc.y * q4.y + acc.z * q4.z + acc.w * q4.w;
            float sk = acc.x * k4.x + acc.y * k4.y + acc.z * k4.z + acc.w * k4.w;
            #pragma unroll
            for (int off = 16; off; off >>= 1) {
                sq += __shfl_down_sync(0xffffffffu, sq, off);
                sk += __shfl_down_sync(0xffffffffu, sk, off);
            }
            if (lane == 0) {
                g_NQ2[node * RELS + r] = sq;
                g_NK2[node * RELS + r] = sk;
            }
        }
    }
}

// ---------------- launch ----------------
extern "C" void kernel_launch(void* const* d_in, const int* in_sizes, int n_in,
                              void* d_out, int out_size) {
    const float* x   = (const float*)d_in[0];
    const int*   ei  = (const int*)d_in[1];
    const int*   et  = (const int*)d_in[2];
    const float* ea  = (const float*)d_in[3];
    const float* w1  = (const float*)d_in[4];
    const float* q1  = (const float*)d_in[5];
    const float* k1  = (const float*)d_in[6];
    const float* e1  = (const float*)d_in[7];
    const float* we1 = (const float*)d_in[8];
    const float* b1  = (const float*)d_in[9];
    const float* w2  = (const float*)d_in[10];
    const float* q2  = (const float*)d_in[11];
    const float* k2  = (const float*)d_in[12];
    const float* e2  = (const float*)d_in[13];
    const float* we2 = (const float*)d_in[14];
    const float* b2  = (const float*)d_in[15];

    int Nn = in_sizes[0] / F;
    int Ecnt = in_sizes[2];
    const int* srcp = ei;
    const int* dstp = ei + Ecnt;
    float* outp = (float*)d_out;

    int nodeBlocks  = (Nn + 255) / 256;
    int edgeBlocks  = (Ecnt + 255) / 256;
    int scanBlocks  = (Nn + 255) / 256;
    dim3 gemmGrid((Nn + 127) / 128, RELS);
    int warpNodeBlk = (Nn + 7) / 8;

    cudaFuncSetAttribute(gemm_mma_kernel, cudaFuncAttributeMaxDynamicSharedMemorySize,
                         GEMM_SMEM_TOTAL);

    void* hptr = nullptr;
    cudaGetSymbolAddress(&hptr, g_H);

    prep_kernel<<<(4 * RELS * F + 2 + 255) / 256, 256>>>(w1, q1, k1, w2, q2, k2,
                                                         we1, e1, we2, e2);
    prepw_kernel<<<(2 * RELS * 64 * 128 + 255) / 256, 256>>>(w1, w2);

    // ----- CSR build (once; reused by both layers) -----
    zero_cnt_kernel<<<nodeBlocks, 256>>>(Nn);
    hist_kernel<<<edgeBlocks, 256>>>(dstp, Ecnt);
    scan1_kernel<<<scanBlocks, 256>>>(Nn);
    scan2_kernel<<<1, 1024>>>(scanBlocks);
    scan3_kernel<<<(Nn + 256) / 256, 256>>>(Nn, Ecnt);
    scatter_kernel<<<edgeBlocks, 256>>>(srcp, dstp, et, ea, Ecnt, Nn);

    // ----- layer 1 (agg tail computes layer-2 split + logits into NQ2/NK2) -----
    split_nqnk_kernel<<<warpNodeBlk, 256>>>(x, Nn);
    gemm_mma_kernel<<<gemmGrid, 256, GEMM_SMEM_TOTAL>>>(0, Nn);
    fused_agg_kernel<<<warpNodeBlk, 256>>>((float*)hptr, b1, 0, 1, 1, 0, Nn);

    // ----- layer 2 -----
    gemm_mma_kernel<<<gemmGrid, 256, GEMM_SMEM_TOTAL>>>(1, Nn);
    fused_agg_kernel<<<warpNodeBlk, 256>>>(outp, b2, 1, 0, 0, 1, Nn);

    (void)n_in; (void)out_size;
}

// round 10
// speedup vs baseline: 1.1813x; 1.0383x over previous
#include <cuda_runtime.h>
#include <cuda_bf16.h>
#include <cstdint>

#define RELS 3
#define F 128
#define NMAX 50000
#define EMAX 800000
#define WSLOTS 64                                    // smem-staged edges per node

// ---------------- scratch (static device globals; no allocation) ----------------
__device__ float    g_XW[(size_t)RELS * NMAX * F];   // [r][n][f]  76.8 MB
__device__ float    g_H[(size_t)NMAX * F];           // layer-1 output
__device__ uint32_t g_XHI[(size_t)NMAX * 64];        // bf16x2 pairs, hi part
__device__ uint32_t g_XLO[(size_t)NMAX * 64];        // bf16x2 pairs, lo part
__device__ uint32_t g_WHI[2 * RELS * 128 * 64];      // W^T split hi: [layer][r][n][kpair]
__device__ uint32_t g_WLO[2 * RELS * 128 * 64];
__device__ float    g_NQ[NMAX * RELS];               // layer-1 logits
__device__ float    g_NK[NMAX * RELS];
__device__ float    g_NQ2[NMAX * RELS];              // layer-2 logits (written by L1 agg tail)
__device__ float    g_NK2[NMAX * RELS];
__device__ float    g_EX[EMAX];                      // overflow path only
__device__ float    g_WQ[2 * RELS * F];
__device__ float    g_WK[2 * RELS * F];
__device__ float    g_CE[2];
// CSR scratch
__device__ int   g_CNT[NMAX];
__device__ int   g_ROWPTR[NMAX + 1];
__device__ int   g_PART[NMAX];
__device__ int   g_BSUM[1024];
__device__ int4  g_EDGE[EMAX];                       // {nkidx, rowidx, sea_bits, 0}

__device__ __forceinline__ uint32_t pack_split_hi(float x, float y) {
    __nv_bfloat16 hx = __float2bfloat16_rn(x);
    __nv_bfloat16 hy = __float2bfloat16_rn(y);
    return ((uint32_t)*(uint16_t*)&hy << 16) | (uint32_t)*(uint16_t*)&hx;
}
__device__ __forceinline__ uint32_t pack_split_lo(float x, float y) {
    __nv_bfloat16 hx = __float2bfloat16_rn(x);
    __nv_bfloat16 hy = __float2bfloat16_rn(y);
    __nv_bfloat16 lx = __float2bfloat16_rn(x - __bfloat162float(hx));
    __nv_bfloat16 ly = __float2bfloat16_rn(y - __bfloat162float(hy));
    return ((uint32_t)*(uint16_t*)&ly << 16) | (uint32_t)*(uint16_t*)&lx;
}

// ---------------- prep: wq/wk vectors + edge scalar ----------------
__global__ void prep_kernel(const float* __restrict__ w1, const float* __restrict__ q1,
                            const float* __restrict__ k1,
                            const float* __restrict__ w2, const float* __restrict__ q2,
                            const float* __restrict__ k2,
                            const float* __restrict__ we1, const float* __restrict__ e1,
                            const float* __restrict__ we2, const float* __restrict__ e2) {
    int idx = blockIdx.x * blockDim.x + threadIdx.x;
    if (idx < 4 * RELS * F) {
        int which = idx / (RELS * F);
        int rem   = idx % (RELS * F);
        const float* w = (which < 2) ? w1 : w2;
        const float* v = (which == 0) ? q1 : (which == 1) ? k1 : (which == 2) ? q2 : k2;
        const float* row = w + (size_t)rem * F;
        float s = 0.f;
        #pragma unroll 8
        for (int o = 0; o < F; o++) s += row[o] * v[o];
        float* d = (which == 0) ? g_WQ
                 : (which == 1) ? g_WK
                 : (which == 2) ? (g_WQ + RELS * F)
                 : (g_WK + RELS * F);
        d[rem] = s;
    } else if (idx == 4 * RELS * F) {
        float s = 0.f;
        for (int o = 0; o < F; o++) s += we1[o] * e1[o];
        g_CE[0] = s;
    } else if (idx == 4 * RELS * F + 1) {
        float s = 0.f;
        for (int o = 0; o < F; o++) s += we2[o] * e2[o];
        g_CE[1] = s;
    }
}

// ---------------- prepw: split W (transposed) to bf16 hi/lo once ----------------
__global__ void prepw_kernel(const float* __restrict__ w1, const float* __restrict__ w2) {
    int idx = blockIdx.x * blockDim.x + threadIdx.x;   // total 2*3*64*128
    if (idx >= 2 * RELS * 64 * 128) return;
    int n     = idx & 127;
    int p     = (idx >> 7) & 63;
    int r     = (idx >> 13) % RELS;
    int layer = idx / (RELS * 64 * 128);
    const float* W = (layer == 0) ? w1 : w2;
    const float* Wr = W + (size_t)r * F * F;
    float vx = Wr[(size_t)(2 * p) * F + n];
    float vy = Wr[(size_t)(2 * p + 1) * F + n];
    size_t o = ((size_t)(layer * RELS + r) * 128 + n) * 64 + p;
    g_WHI[o] = pack_split_hi(vx, vy);
    g_WLO[o] = pack_split_lo(vx, vy);
}

// ---------------- CSR build ----------------
__global__ void zero_cnt_kernel(int Nn) {
    int i = blockIdx.x * blockDim.x + threadIdx.x;
    if (i < Nn) g_CNT[i] = 0;
}
__global__ void hist_kernel(const int* __restrict__ dst, int Ecnt) {
    int e = blockIdx.x * blockDim.x + threadIdx.x;
    if (e < Ecnt) atomicAdd(&g_CNT[dst[e]], 1);
}
__global__ void scan1_kernel(int Nn) {
    __shared__ int sh[256];
    int i = blockIdx.x * 256 + threadIdx.x;
    int v = (i < Nn) ? g_CNT[i] : 0;
    sh[threadIdx.x] = v;
    __syncthreads();
    #pragma unroll
    for (int off = 1; off < 256; off <<= 1) {
        int t = (threadIdx.x >= off) ? sh[threadIdx.x - off] : 0;
        __syncthreads();
        sh[threadIdx.x] += t;
        __syncthreads();
    }
    if (i < Nn) g_PART[i] = sh[threadIdx.x] - v;
    if (threadIdx.x == 255) g_BSUM[blockIdx.x] = sh[255];
}
__global__ void scan2_kernel(int nb) {
    __shared__ int sh[1024];
    int v = (threadIdx.x < nb) ? g_BSUM[threadIdx.x] : 0;
    sh[threadIdx.x] = v;
    __syncthreads();
    #pragma unroll
    for (int off = 1; off < 1024; off <<= 1) {
        int t = (threadIdx.x >= off) ? sh[threadIdx.x - off] : 0;
        __syncthreads();
        sh[threadIdx.x] += t;
        __syncthreads();
    }
    if (threadIdx.x < nb) g_BSUM[threadIdx.x] = sh[threadIdx.x] - v;
}
__global__ void scan3_kernel(int Nn, int Ecnt) {
    int i = blockIdx.x * blockDim.x + threadIdx.x;
    if (i < Nn) {
        g_ROWPTR[i] = g_PART[i] + g_BSUM[i >> 8];
        g_CNT[i] = 0;
    }
    if (i == Nn) g_ROWPTR[Nn] = Ecnt;
}
__global__ void scatter_kernel(const int* __restrict__ src, const int* __restrict__ dst,
                               const int* __restrict__ et, const float* __restrict__ ea,
                               int Ecnt, int Nn) {
    int e = blockIdx.x * blockDim.x + threadIdx.x;
    if (e >= Ecnt) return;
    int d = dst[e];
    int pos = g_ROWPTR[d] + atomicAdd(&g_CNT[d], 1);
    int s = src[e], t = et[e];
    g_EDGE[pos] = make_int4(s * RELS + t, t * Nn + s, __float_as_int(ea[e]), 0);
}

// ------- fused: x -> bf16 hi/lo split + layer-1 attention logits; warp per node -------
__global__ __launch_bounds__(256) void split_nqnk_kernel(const float* __restrict__ xin, int Nn) {
    __shared__ float swq[RELS * F];
    __shared__ float swk[RELS * F];
    for (int i = threadIdx.x; i < RELS * F; i += blockDim.x) {
        swq[i] = g_WQ[i];
        swk[i] = g_WK[i];
    }
    __syncthreads();

    int warp = (blockIdx.x * blockDim.x + threadIdx.x) >> 5;
    int lane = threadIdx.x & 31;
    if (warp >= Nn) return;

    float4 v = ((const float4*)(xin + (size_t)warp * F))[lane];

    uint32_t* xh = g_XHI + (size_t)warp * 64;
    uint32_t* xl = g_XLO + (size_t)warp * 64;
    xh[lane * 2]     = pack_split_hi(v.x, v.y);
    xh[lane * 2 + 1] = pack_split_hi(v.z, v.w);
    xl[lane * 2]     = pack_split_lo(v.x, v.y);
    xl[lane * 2 + 1] = pack_split_lo(v.z, v.w);

    #pragma unroll
    for (int r = 0; r < RELS; r++) {
        const float4 q4 = ((const float4*)(swq + r * F))[lane];
        const float4 k4 = ((const float4*)(swk + r * F))[lane];
        float sq = v.x * q4.x + v.y * q4.y + v.z * q4.z + v.w * q4.w;
        float sk = v.x * k4.x + v.y * k4.y + v.z * k4.z + v.w * k4.w;
        #pragma unroll
        for (int off = 16; off; off >>= 1) {
            sq += __shfl_down_sync(0xffffffffu, sq, off);
            sk += __shfl_down_sync(0xffffffffu, sk, off);
        }
        if (lane == 0) {
            g_NQ[warp * RELS + r] = sq;
            g_NK[warp * RELS + r] = sk;
        }
    }
}

// ====== mma.sync bf16 GEMM (pre-split operands, all 3 relations per CTA) ======
#define APITCH 68
#define TILE_WORDS (128 * APITCH)
#define GEMM_SMEM_TOTAL (4 * TILE_WORDS * 4)

__device__ __forceinline__ void mma16816(float* d, const uint32_t* a, const uint32_t* b) {
    asm volatile("mma.sync.aligned.m16n8k16.row.col.f32.bf16.bf16.f32 "
                 "{%0,%1,%2,%3}, {%4,%5,%6,%7}, {%8,%9}, {%0,%1,%2,%3};"
                 : "+f"(d[0]), "+f"(d[1]), "+f"(d[2]), "+f"(d[3])
                 : "r"(a[0]), "r"(a[1]), "r"(a[2]), "r"(a[3]), "r"(b[0]), "r"(b[1]));
}

__global__ __launch_bounds__(256) void gemm_mma_kernel(int layer, int Nn) {
    extern __shared__ uint32_t smem[];
    uint32_t* sAhi = smem;
    uint32_t* sAlo = smem + TILE_WORDS;
    uint32_t* sBhi = smem + 2 * TILE_WORDS;
    uint32_t* sBlo = smem + 3 * TILE_WORDS;

    int rowBase = blockIdx.x * 128;
    int tid = threadIdx.x;

    // ---- A tiles: loaded ONCE, reused for all 3 relations ----
    for (int idx = tid; idx < 128 * 64; idx += 256) {
        int row = idx >> 6;
        int pair = idx & 63;
        int grow = rowBase + row;
        uint32_t hi = 0, lo = 0;
        if (grow < Nn) {
            hi = g_XHI[(size_t)grow * 64 + pair];
            lo = g_XLO[(size_t)grow * 64 + pair];
        }
        sAhi[row * APITCH + pair] = hi;
        sAlo[row * APITCH + pair] = lo;
    }

    int wid = tid >> 5;
    int lane = tid & 31;
    int warpM = wid & 3;
    int warpN = wid >> 2;
    int g = lane >> 2;
    int tig = lane & 3;

    for (int r = 0; r < RELS; r++) {
        __syncthreads();   // A ready (r=0) / prior compute done before B overwrite
        {
            const uint32_t* wh = g_WHI + (size_t)(layer * RELS + r) * 128 * 64;
            const uint32_t* wl = g_WLO + (size_t)(layer * RELS + r) * 128 * 64;
            for (int idx = tid; idx < 128 * 64; idx += 256) {
                int n = idx >> 6;
                int p = idx & 63;
                sBhi[n * APITCH + p] = wh[idx];
                sBlo[n * APITCH + p] = wl[idx];
            }
        }
        __syncthreads();

        float acc[2][8][4];
        #pragma unroll
        for (int mt = 0; mt < 2; mt++)
            #pragma unroll
            for (int nt = 0; nt < 8; nt++)
                #pragma unroll
                for (int c = 0; c < 4; c++) acc[mt][nt][c] = 0.f;

        #pragma unroll
        for (int split = 0; split < 3; split++) {
            const uint32_t* As = (split == 2) ? sAlo : sAhi;
            const uint32_t* Bs = (split == 1) ? sBlo : sBhi;
            #pragma unroll
            for (int ks = 0; ks < 8; ks++) {
                int kp = ks * 8 + tig;
                uint32_t a[2][4];
                #pragma unroll
                for (int mt = 0; mt < 2; mt++) {
                    int row = warpM * 32 + mt * 16;
                    a[mt][0] = As[(row + g) * APITCH + kp];
                    a[mt][1] = As[(row + g + 8) * APITCH + kp];
                    a[mt][2] = As[(row + g) * APITCH + kp + 4];
                    a[mt][3] = As[(row + g + 8) * APITCH + kp + 4];
                }
                uint32_t b[8][2];
                #pragma unroll
                for (int nt = 0; nt < 8; nt++) {
                    int n = warpN * 64 + nt * 8 + g;
                    b[nt][0] = Bs[n * APITCH + kp];
                    b[nt][1] = Bs[n * APITCH + kp + 4];
                }
                #pragma unroll
                for (int mt = 0; mt < 2; mt++)
                    #pragma unroll
                    for (int nt = 0; nt < 8; nt++)
                        mma16816(acc[mt][nt], a[mt], b[nt]);
            }
        }

        float* outp = g_XW + (size_t)r * Nn * F;
        #pragma unroll
        for (int mt = 0; mt < 2; mt++) {
            int row0 = rowBase + warpM * 32 + mt * 16 + g;
            int row1 = row0 + 8;
            #pragma unroll
            for (int nt = 0; nt < 8; nt++) {
                int col = warpN * 64 + nt * 8 + tig * 2;
                if (row0 < Nn)
                    *(float2*)(outp + (size_t)row0 * F + col) = make_float2(acc[mt][nt][0], acc[mt][nt][1]);
                if (row1 < Nn)
                    *(float2*)(outp + (size_t)row1 * F + col) = make_float2(acc[mt][nt][2], acc[mt][nt][3]);
            }
        }
    }
}

// -------- fused softmax + aggregate + bias(+relu) [+ next-layer split & logits] --------
// warp per dst node; (rowidx, ex) staged in shared for the first WSLOTS edges.
__global__ __launch_bounds__(256) void fused_agg_kernel(float* __restrict__ outp,
                                                        const float* __restrict__ bias,
                                                        int layer, int relu, int donext,
                                                        int use2, int Nn) {
    __shared__ float swq[RELS * F];
    __shared__ float swk[RELS * F];
    __shared__ int   srow[8][WSLOTS];
    __shared__ float sex[8][WSLOTS];
    if (donext) {
        const float* WQ = g_WQ + (layer + 1) * RELS * F;
        const float* WK = g_WK + (layer + 1) * RELS * F;
        for (int i = threadIdx.x; i < RELS * F; i += blockDim.x) {
            swq[i] = WQ[i];
            swk[i] = WK[i];
        }
        __syncthreads();
    }

    int wslot = threadIdx.x >> 5;
    int node = (blockIdx.x * blockDim.x + threadIdx.x) >> 5;
    int lane = threadIdx.x & 31;
    if (node >= Nn) return;

    const float* NQ = use2 ? g_NQ2 : g_NQ;
    const float* NK = use2 ? g_NK2 : g_NK;

    int start = g_ROWPTR[node];
    int end   = g_ROWPTR[node + 1];
    float ce  = g_CE[layer];
    float nq0 = NQ[node * RELS + 0];
    float nq1 = NQ[node * RELS + 1];
    float nq2 = NQ[node * RELS + 2];

    // phase 1: lane-parallel exp + denominator; stage (rowidx, ex) in smem
    float denom = 0.f;
    for (int i = start + lane; i < end; i += 32) {
        int4 e = g_EDGE[i];
        int t = e.x - (e.x / RELS) * RELS;
        float nq = (t == 0) ? nq0 : (t == 1) ? nq1 : nq2;
        float a = nq + NK[e.x] + ce * __int_as_float(e.z);
        a = (a > 0.f) ? a : 0.2f * a;
        float ex = expf(a);
        int k = i - start;
        if (k < WSLOTS) {
            srow[wslot][k] = e.y;
            sex[wslot][k]  = ex;
        } else {
            g_EX[i] = ex;            // rare overflow path
        }
        denom += ex;
    }
    #pragma unroll
    for (int off = 16; off; off >>= 1)
        denom += __shfl_xor_sync(0xffffffffu, denom, off);
    float inv = 1.f / (denom + 1e-16f);
    __syncwarp();

    // phase 2: warp-per-edge gather; metadata from smem (broadcast LDS)
    int deg = end - start;
    int m = deg < WSLOTS ? deg : WSLOTS;
    float4 acc = make_float4(0.f, 0.f, 0.f, 0.f);
    int k = 0;
    for (; k + 3 < m; k += 4) {
        float at0 = sex[wslot][k]     * inv;
        float at1 = sex[wslot][k + 1] * inv;
        float at2 = sex[wslot][k + 2] * inv;
        float at3 = sex[wslot][k + 3] * inv;
        float4 v0 = ((const float4*)(g_XW + (size_t)srow[wslot][k]     * F))[lane];
        float4 v1 = ((const float4*)(g_XW + (size_t)srow[wslot][k + 1] * F))[lane];
        float4 v2 = ((const float4*)(g_XW + (size_t)srow[wslot][k + 2] * F))[lane];
        float4 v3 = ((const float4*)(g_XW + (size_t)srow[wslot][k + 3] * F))[lane];
        acc.x += at0 * v0.x + at1 * v1.x + at2 * v2.x + at3 * v3.x;
        acc.y += at0 * v0.y + at1 * v1.y + at2 * v2.y + at3 * v3.y;
        acc.z += at0 * v0.z + at1 * v1.z + at2 * v2.z + at3 * v3.z;
        acc.w += at0 * v0.w + at1 * v1.w + at2 * v2.w + at3 * v3.w;
    }
    for (; k < m; k++) {
        float at = sex[wslot][k] * inv;
        float4 v = ((const float4*)(g_XW + (size_t)srow[wslot][k] * F))[lane];
        acc.x += at * v.x;
        acc.y += at * v.y;
        acc.z += at * v.z;
        acc.w += at * v.w;
    }
    // overflow tail (degree > WSLOTS): read metadata from global
    for (int i = start + WSLOTS; i < end; i++) {
        float at = g_EX[i] * inv;
        int r0 = ((const int*)g_EDGE)[4 * i + 1];
        float4 v = ((const float4*)(g_XW + (size_t)r0 * F))[lane];
        acc.x += at * v.x;
        acc.y += at * v.y;
        acc.z += at * v.z;
        acc.w += at * v.w;
    }

    const float4 b = *(const float4*)(bias + lane * 4);
    acc.x += b.x; acc.y += b.y; acc.z += b.z; acc.w += b.w;
    if (relu) {
        acc.x = acc.x > 0.f ? acc.x : 0.f;
        acc.y = acc.y > 0.f ? acc.y : 0.f;
        acc.z = acc.z > 0.f ? acc.z : 0.f;
        acc.w = acc.w > 0.f ? acc.w : 0.f;
    }
    *(float4*)(outp + (size_t)node * F + lane * 4) = acc;

    // fused tail: bf16 split + next-layer logits on the h row; writes NQ2/NK2 only
    if (donext) {
        uint32_t* xh = g_XHI + (size_t)node * 64;
        uint32_t* xl = g_XLO + (size_t)node * 64;
        xh[lane * 2]     = pack_split_hi(acc.x, acc.y);
        xh[lane * 2 + 1] = pack_split_hi(acc.z, acc.w);
        xl[lane * 2]     = pack_split_lo(acc.x, acc.y);
        xl[lane * 2 + 1] = pack_split_lo(acc.z, acc.w);

        #pragma unroll
        for (int r = 0; r < RELS; r++) {
            const float4 q4 = ((const float4*)(swq + r * F))[lane];
            const float4 k4 = ((const float4*)(swk + r * F))[lane];
            float sq = acc.x * q4.x + acc.y * q4.y + acc.z * q4.z + acc.w * q4.w;
            float sk = acc.x * k4.x + acc.y * k4.y + acc.z * k4.z + acc.w * k4.w;
            #pragma unroll
            for (int off = 16; off; off >>= 1) {
                sq += __shfl_down_sync(0xffffffffu, sq, off);
                sk += __shfl_down_sync(0xffffffffu, sk, off);
            }
            if (lane == 0) {
                g_NQ2[node * RELS + r] = sq;
                g_NK2[node * RELS + r] = sk;
            }
        }
    }
}

// ---------------- launch ----------------
extern "C" void kernel_launch(void* const* d_in, const int* in_sizes, int n_in,
                              void* d_out, int out_size) {
    const float* x   = (const float*)d_in[0];
    const int*   ei  = (const int*)d_in[1];
    const int*   et  = (const int*)d_in[2];
    const float* ea  = (const float*)d_in[3];
    const float* w1  = (const float*)d_in[4];
    const float* q1  = (const float*)d_in[5];
    const float* k1  = (const float*)d_in[6];
    const float* e1  = (const float*)d_in[7];
    const float* we1 = (const float*)d_in[8];
    const float* b1  = (const float*)d_in[9];
    const float* w2  = (const float*)d_in[10];
    const float* q2  = (const float*)d_in[11];
    const float* k2  = (const float*)d_in[12];
    const float* e2  = (const float*)d_in[13];
    const float* we2 = (const float*)d_in[14];
    const float* b2  = (const float*)d_in[15];

    int Nn = in_sizes[0] / F;
    int Ecnt = in_sizes[2];
    const int* srcp = ei;
    const int* dstp = ei + Ecnt;
    float* outp = (float*)d_out;

    int nodeBlocks  = (Nn + 255) / 256;
    int edgeBlocks  = (Ecnt + 255) / 256;
    int scanBlocks  = (Nn + 255) / 256;
    int gemmBlocks  = (Nn + 127) / 128;
    int warpNodeBlk = (Nn + 7) / 8;

    cudaFuncSetAttribute(gemm_mma_kernel, cudaFuncAttributeMaxDynamicSharedMemorySize,
                         GEMM_SMEM_TOTAL);

    void* hptr = nullptr;
    cudaGetSymbolAddress(&hptr, g_H);

    prep_kernel<<<(4 * RELS * F + 2 + 255) / 256, 256>>>(w1, q1, k1, w2, q2, k2,
                                                         we1, e1, we2, e2);
    prepw_kernel<<<(2 * RELS * 64 * 128 + 255) / 256, 256>>>(w1, w2);

    // ----- CSR build (once; reused by both layers) -----
    zero_cnt_kernel<<<nodeBlocks, 256>>>(Nn);
    hist_kernel<<<edgeBlocks, 256>>>(dstp, Ecnt);
    scan1_kernel<<<scanBlocks, 256>>>(Nn);
    scan2_kernel<<<1, 1024>>>(scanBlocks);
    scan3_kernel<<<(Nn + 256) / 256, 256>>>(Nn, Ecnt);
    scatter_kernel<<<edgeBlocks, 256>>>(srcp, dstp, et, ea, Ecnt, Nn);

    // ----- layer 1 (agg tail computes layer-2 split + logits into NQ2/NK2) -----
    split_nqnk_kernel<<<warpNodeBlk, 256>>>(x, Nn);
    gemm_mma_kernel<<<gemmBlocks, 256, GEMM_SMEM_TOTAL>>>(0, Nn);
    fused_agg_kernel<<<warpNodeBlk, 256>>>((float*)hptr, b1, 0, 1, 1, 0, Nn);

    // ----- layer 2 -----
    gemm_mma_kernel<<<gemmBlocks, 256, GEMM_SMEM_TOTAL>>>(1, Nn);
    fused_agg_kernel<<<warpNodeBlk, 256>>>(outp, b2, 1, 0, 0, 1, Nn);

    (void)n_in; (void)out_size;
}